// round 4
// baseline (speedup 1.0000x reference)
#include <cuda_runtime.h>

// Quanvolution via closed-form expectation values (Heisenberg picture):
//   a0 = x0 + w0, a1 = x1 + w1
//   <Z0> = cos(w2)*cos(a0); <Z1> = cos(a1); <Z2> = cos(a0)*cos(x2)
//   <Z3> = cos(w3)*cos(a0)*cos(x2)*cos(x3)
//
// Input  x: [32,1,512,512] fp32 -> Output [32,4,256,256] fp32
//
// 2^18 threads; each thread handles items {i, i+2^18, i+2*2^18, i+3*2^18}.
// Because the stride is 2^18 = 8 batches of work, consecutive items differ
// ONLY in batch index (+8): input ptr advances by 8*262144 floats, output ptr
// by 8*4*65536 floats. Fully unrolled 4 iterations, depth-2 load pipeline,
// zero per-iteration address recomputation.

#define HP      256
#define WP      256
#define PLANE   (HP * WP)                 // 65536
#define NTHREADS (1 << 18)                // 262,144
#define IN_STEP  (8u * 512u * 512u)       // 8 batches of input floats
#define OUT_STEP (8u * 4u * PLANE)        // 8 batches of output floats

__global__ __launch_bounds__(256, 6)
void quanv_kernel(const float* __restrict__ x,
                  const float* __restrict__ w,
                  float* __restrict__ out) {
    int i = blockIdx.x * blockDim.x + threadIdx.x;   // [0, 2^18)
    int kk = i & 127;            // float4 index within row (2 patches)
    int j  = (i >> 7) & 255;     // patch row
    int b  = i >> 15;            // batch in [0,8)

    const float w0  = __ldg(w + 0);
    const float w1  = __ldg(w + 1);
    const float cw2 = __cosf(__ldg(w + 2));
    const float cw3 = __cosf(__ldg(w + 3));

    const float4* p = reinterpret_cast<const float4*>(
        x + ((size_t)b * 512 + 2 * (size_t)j) * 512) + kk;
    float* o = out + (((size_t)b * 4) * HP + j) * WP + 2 * (size_t)kk;

    // depth-2 pipeline over exactly 4 iterations
    float4 r0 = __ldg(p);
    float4 r1 = __ldg(p + 128);

    #pragma unroll
    for (int k = 0; k < 4; k++) {
        float4 n0, n1;
        if (k < 3) {
            const float4* np = p + (IN_STEP / 4);
            n0 = __ldg(np);
            n1 = __ldg(np + 128);
            p = np;
        }

        // patch A: (r0.x, r0.y, r1.x, r1.y); patch B: (r0.z, r0.w, r1.z, r1.w)
        float c0a = __cosf(r0.x + w0);
        float c1a = __cosf(r0.y + w1);
        float c2a = __cosf(r1.x);
        float c3a = __cosf(r1.y);

        float c0b = __cosf(r0.z + w0);
        float c1b = __cosf(r0.w + w1);
        float c2b = __cosf(r1.z);
        float c3b = __cosf(r1.w);

        float e2a = c0a * c2a;
        float e2b = c0b * c2b;

        *reinterpret_cast<float2*>(o)             = make_float2(cw2 * c0a, cw2 * c0b);
        *reinterpret_cast<float2*>(o + PLANE)     = make_float2(c1a,        c1b);
        *reinterpret_cast<float2*>(o + 2 * PLANE) = make_float2(e2a,        e2b);
        *reinterpret_cast<float2*>(o + 3 * PLANE) = make_float2(cw3 * e2a * c3a,
                                                                cw3 * e2b * c3b);
        if (k < 3) {
            o += OUT_STEP;
            r0 = n0;
            r1 = n1;
        }
    }
}

extern "C" void kernel_launch(void* const* d_in, const int* in_sizes, int n_in,
                              void* d_out, int out_size) {
    const float* x = (const float*)d_in[0];
    const float* w = (const float*)d_in[1];
    float* out = (float*)d_out;

    quanv_kernel<<<NTHREADS / 256, 256>>>(x, w, out);   // 1024 CTAs
}